// round 14
// baseline (speedup 1.0000x reference)
#include <cuda_runtime.h>
#include <cuda_bf16.h>
#include <cstdio>

#define N_NODES 50000
#define N_EDGES 800000
#define N_GRAPHS 2048
#define HID 128
#define IN_DIM 7
#define SCB 1024
#define NSCB ((N_NODES + SCB - 1) / SCB)   // 49
#define NODE_TILES ((N_NODES + 63) / 64)   // 782
#define PERSIST_BLOCKS 444                 // 148 SMs * 3 blocks

typedef unsigned short ushort_t;

// ------------------- scratch (device globals; no allocation) -------------------
__device__ float g_hpre[N_NODES * HID];          // pre-BN features (buffer A)
__device__ float g_hpre2[N_NODES * HID];         // pre-BN features (buffer B)
__device__ float g_stats[2 * HID];
__device__ float g_scale[HID];
__device__ float g_shift[HID];
// CSC (edges grouped by dst): sorted edge records {src_bits, ea0, ea1, ea2}
__device__ int g_cnti[N_NODES];
__device__ int g_off[N_NODES + 1];
__device__ int g_fill[N_NODES];
__device__ float4 g_edge[N_EDGES];
__device__ int g_bsum[64];
__device__ int g_tile[4];                        // work-stealing counters (per layer)
// weight fragments: 5 matrices (W12,W21,W22,W31,W32), [nt16][ks8][lane32] uint2
__device__ uint2 g_wfhi[5 * 4096];
__device__ uint2 g_wflo[5 * 4096];

__device__ __forceinline__ void mma16816(float acc[4],
                                         unsigned a0, unsigned a1, unsigned a2, unsigned a3,
                                         unsigned b0, unsigned b1) {
    asm volatile("mma.sync.aligned.m16n8k16.row.col.f32.bf16.bf16.f32 "
                 "{%0,%1,%2,%3},{%4,%5,%6,%7},{%8,%9},{%0,%1,%2,%3};"
                 : "+f"(acc[0]), "+f"(acc[1]), "+f"(acc[2]), "+f"(acc[3])
                 : "r"(a0), "r"(a1), "r"(a2), "r"(a3), "r"(b0), "r"(b1));
}

__device__ __forceinline__ void pk_split(float a, float b, unsigned& hi, unsigned& lo) {
    __nv_bfloat16 ha = __float2bfloat16(a);
    __nv_bfloat16 hb = __float2bfloat16(b);
    __nv_bfloat16 la = __float2bfloat16(a - __bfloat162float(ha));
    __nv_bfloat16 lb = __float2bfloat16(b - __bfloat162float(hb));
    hi = (unsigned)__bfloat16_as_ushort(ha) | ((unsigned)__bfloat16_as_ushort(hb) << 16);
    lo = (unsigned)__bfloat16_as_ushort(la) | ((unsigned)__bfloat16_as_ushort(lb) << 16);
}

// ------------------- weight fragment prep -------------------
__global__ void prep_wfrag(const float* W12, const float* W21, const float* W22,
                           const float* W31, const float* W32) {
    const float* Ws[5] = {W12, W21, W22, W31, W32};
    int m = blockIdx.y;
    const float* W = Ws[m];
    int idx = blockIdx.x * 256 + threadIdx.x;
    int lane = idx & 31, ks = (idx >> 5) & 7, nt = idx >> 8;
    int n = nt * 8 + (lane >> 2);
    int k0 = ks * 16 + (lane & 3) * 2;
    unsigned h0, l0, h1, l1;
    pk_split(W[k0 * HID + n], W[(k0 + 1) * HID + n], h0, l0);
    pk_split(W[(k0 + 8) * HID + n], W[(k0 + 9) * HID + n], h1, l1);
    g_wfhi[m * 4096 + idx] = make_uint2(h0, h1);
    g_wflo[m * 4096 + idx] = make_uint2(l0, l1);
}

// ------------------- utility -------------------
__global__ void zero_misc() {
    int i = blockIdx.x * blockDim.x + threadIdx.x;
    if (i < 2 * HID) g_stats[i] = 0.f;
    if (i < N_NODES) g_cnti[i] = 0;
    if (i < 4) g_tile[i] = 0;
}

// ------------------- CSC build -------------------
__global__ void csr_hist(const int* __restrict__ ei) {
    int e = blockIdx.x * blockDim.x + threadIdx.x;
    if (e < N_EDGES) atomicAdd(&g_cnti[ei[N_EDGES + e]], 1);
}

__global__ void scan1() {
    __shared__ int warpsum[32];
    int i = blockIdx.x * SCB + threadIdx.x;
    int lane = threadIdx.x & 31, wid = threadIdx.x >> 5;
    int v = (i < N_NODES) ? g_cnti[i] : 0;
    int s = v;
#pragma unroll
    for (int o = 1; o < 32; o <<= 1) {
        int t = __shfl_up_sync(0xffffffffu, s, o);
        if (lane >= o) s += t;
    }
    if (lane == 31) warpsum[wid] = s;
    __syncthreads();
    if (wid == 0) {
        int ws = warpsum[lane];
#pragma unroll
        for (int o = 1; o < 32; o <<= 1) {
            int t = __shfl_up_sync(0xffffffffu, ws, o);
            if (lane >= o) ws += t;
        }
        warpsum[lane] = ws;
    }
    __syncthreads();
    int total = s + (wid > 0 ? warpsum[wid - 1] : 0);
    if (i < N_NODES) g_off[i] = total - v;   // exclusive within block
    if (threadIdx.x == SCB - 1) g_bsum[blockIdx.x] = total;
}

// scan3 with scan2 merged: each block prefix-sums the 49 block sums locally.
__global__ void scan3() {
    __shared__ int bs[64];
    int tid = threadIdx.x;
    if (tid < 64) bs[tid] = (tid < NSCB) ? g_bsum[tid] : 0;
    __syncthreads();
    for (int o = 1; o < 64; o <<= 1) {
        int t = (tid < 64 && tid >= o) ? bs[tid - o] : 0;
        __syncthreads();
        if (tid < 64) bs[tid] += t;
        __syncthreads();
    }
    int i = blockIdx.x * blockDim.x + tid;
    if (i < N_NODES) {
        int blk = i / SCB;
        int pre = (blk > 0) ? bs[blk - 1] : 0;
        int o = g_off[i] + pre;
        g_off[i] = o;
        g_fill[i] = o;
    }
    if (i == 0) g_off[N_NODES] = N_EDGES;
}

// scatter sorted edge records: one float4 per edge {src_bits, ea0, ea1, ea2}
__global__ void csr_scatter(const int* __restrict__ ei, const float* __restrict__ ea) {
    int e = blockIdx.x * blockDim.x + threadIdx.x;
    if (e < N_EDGES) {
        int d = ei[N_EDGES + e];
        int s = ei[e];
        float a0 = ea[e * 3], a1 = ea[e * 3 + 1], a2 = ea[e * 3 + 2];
        int p = atomicAdd(&g_fill[d], 1);
        g_edge[p] = make_float4(__int_as_float(s), a0, a1, a2);
    }
}

// ------------------- tensor GEMM core pieces -------------------
#define AROW 136

__device__ __forceinline__ void tensor_gemm(const ushort_t* Ahi, const ushort_t* Alo,
                                            const uint2* __restrict__ wfhi,
                                            const uint2* __restrict__ wflo,
                                            const float* __restrict__ bias,
                                            int warp, int lane, float acc[8][4]) {
    int mw = warp & 3, nh = warp >> 2;
    int grp = lane >> 2, qk = lane & 3;
#pragma unroll
    for (int nt = 0; nt < 8; nt++) {
        int cc = nh * 64 + nt * 8 + qk * 2;
        float b0 = bias[cc], b1v = bias[cc + 1];
        acc[nt][0] = b0; acc[nt][1] = b1v; acc[nt][2] = b0; acc[nt][3] = b1v;
    }
    int arow = (mw * 16 + grp) * AROW;
#pragma unroll 2
    for (int ks = 0; ks < 8; ks++) {
        int ab = arow + ks * 16 + qk * 2;
        unsigned ah0 = *reinterpret_cast<const unsigned*>(Ahi + ab);
        unsigned ah1 = *reinterpret_cast<const unsigned*>(Ahi + ab + 8 * AROW);
        unsigned ah2 = *reinterpret_cast<const unsigned*>(Ahi + ab + 8);
        unsigned ah3 = *reinterpret_cast<const unsigned*>(Ahi + ab + 8 * AROW + 8);
        unsigned al0 = *reinterpret_cast<const unsigned*>(Alo + ab);
        unsigned al1 = *reinterpret_cast<const unsigned*>(Alo + ab + 8 * AROW);
        unsigned al2 = *reinterpret_cast<const unsigned*>(Alo + ab + 8);
        unsigned al3 = *reinterpret_cast<const unsigned*>(Alo + ab + 8 * AROW + 8);
        const uint2* ph = wfhi + ((nh * 8) * 8 + ks) * 32 + lane;
        const uint2* pl = wflo + ((nh * 8) * 8 + ks) * 32 + lane;
#pragma unroll
        for (int nt = 0; nt < 8; nt++) {
            uint2 bh = ph[nt * 256];
            uint2 bl = pl[nt * 256];
            mma16816(acc[nt], ah0, ah1, ah2, ah3, bh.x, bh.y);
            mma16816(acc[nt], ah0, ah1, ah2, ah3, bl.x, bl.y);
            mma16816(acc[nt], al0, al1, al2, al3, bh.x, bh.y);
        }
    }
}

// relu + bf16-split + store acc into (reused) A smem
__device__ __forceinline__ void store_T(ushort_t* Thi, ushort_t* Tlo,
                                        int warp, int lane, float acc[8][4]) {
    int mw = warp & 3, nh = warp >> 2;
    int grp = lane >> 2, qk = lane & 3;
    int r0 = (mw * 16 + grp) * AROW, r1 = r0 + 8 * AROW;
#pragma unroll
    for (int nt = 0; nt < 8; nt++) {
        int cc = nh * 64 + nt * 8 + qk * 2;
        unsigned hi, lo;
        pk_split(fmaxf(acc[nt][0], 0.f), fmaxf(acc[nt][1], 0.f), hi, lo);
        *reinterpret_cast<unsigned*>(Thi + r0 + cc) = hi;
        *reinterpret_cast<unsigned*>(Tlo + r0 + cc) = lo;
        pk_split(fmaxf(acc[nt][2], 0.f), fmaxf(acc[nt][3], 0.f), hi, lo);
        *reinterpret_cast<unsigned*>(Thi + r1 + cc) = hi;
        *reinterpret_cast<unsigned*>(Tlo + r1 + cc) = lo;
    }
}

__device__ __forceinline__ void epilogue(float* __restrict__ hout,
                                         float* ssum, float* ssq, int base,
                                         int warp, int lane, float acc[8][4]) {
    int mw = warp & 3, nh = warp >> 2;
    int grp = lane >> 2, qk = lane & 3;
    int r0 = base + mw * 16 + grp, r1 = r0 + 8;
    bool v0 = r0 < N_NODES, v1 = r1 < N_NODES;
#pragma unroll
    for (int nt = 0; nt < 8; nt++) {
        int cc = nh * 64 + nt * 8 + qk * 2;
        float f0 = acc[nt][0], f1 = acc[nt][1], f2 = acc[nt][2], f3 = acc[nt][3];
        if (v0) *reinterpret_cast<float2*>(hout + (size_t)r0 * HID + cc) = make_float2(f0, f1);
        if (v1) *reinterpret_cast<float2*>(hout + (size_t)r1 * HID + cc) = make_float2(f2, f3);
        float s0 = (v0 ? f0 : 0.f) + (v1 ? f2 : 0.f);
        float s1 = (v0 ? f1 : 0.f) + (v1 ? f3 : 0.f);
        float q0 = (v0 ? f0 * f0 : 0.f) + (v1 ? f2 * f2 : 0.f);
        float q1 = (v0 ? f1 * f1 : 0.f) + (v1 ? f3 * f3 : 0.f);
        atomicAdd(&ssum[cc], s0);
        atomicAdd(&ssum[cc + 1], s1);
        atomicAdd(&ssq[cc], q0);
        atomicAdd(&ssq[cc + 1], q1);
    }
}

// ------------------- FUSED node kernel, layers 2/3 (persistent, work-stealing) ----------
__global__ void __launch_bounds__(256, 3)
node_fused(const float* __restrict__ hsrc, float* __restrict__ hdst, int ctr,
           const float* __restrict__ We, const float* __restrict__ be,
           const uint2* __restrict__ wfhi1, const uint2* __restrict__ wflo1, const float* __restrict__ b1,
           const uint2* __restrict__ wfhi2, const uint2* __restrict__ wflo2, const float* __restrict__ b2) {
    extern __shared__ __align__(16) char smemc[];
    ushort_t* Ahi = reinterpret_cast<ushort_t*>(smemc);
    ushort_t* Alo = Ahi + 64 * AROW;
    float* ssum = reinterpret_cast<float*>(Alo + 64 * AROW);
    float* ssq = ssum + HID;
    __shared__ int s_tile;
    int tid = threadIdx.x;
    int warp = tid >> 5, lane = tid & 31;
    int c = lane * 4;

    float4 w0 = *reinterpret_cast<const float4*>(We + c);
    float4 w1 = *reinterpret_cast<const float4*>(We + HID + c);
    float4 w2 = *reinterpret_cast<const float4*>(We + 2 * HID + c);
    float4 b4 = *reinterpret_cast<const float4*>(be + c);
    float4 sc4 = *reinterpret_cast<const float4*>(g_scale + c);
    float4 sh4 = *reinterpret_cast<const float4*>(g_shift + c);

    for (;;) {
        if (tid == 0) s_tile = atomicAdd(&g_tile[ctr], 1);
        __syncthreads();
        int tile = s_tile;
        if (tile >= NODE_TILES) return;
        int base = tile * 64;
        if (tid < HID) { ssum[tid] = 0.f; ssq[tid] = 0.f; }

        for (int rr = 0; rr < 8; rr++) {
            int r = warp * 8 + rr;
            int n = base + r;
            float ax = 0.f, ay = 0.f, az = 0.f, aw = 0.f;
            if (n < N_NODES) {
                float4 own = *reinterpret_cast<const float4*>(hsrc + (size_t)n * HID + c);
                ax = fmaxf(own.x * sc4.x + sh4.x, 0.f);
                ay = fmaxf(own.y * sc4.y + sh4.y, 0.f);
                az = fmaxf(own.z * sc4.z + sh4.z, 0.f);
                aw = fmaxf(own.w * sc4.w + sh4.w, 0.f);
                int beg = g_off[n], end = g_off[n + 1];
                int j = beg;
                for (; j + 4 <= end; j += 4) {
                    float4 E0 = g_edge[j], E1 = g_edge[j + 1], E2 = g_edge[j + 2], E3 = g_edge[j + 3];
                    float4 h0 = *reinterpret_cast<const float4*>(hsrc + (size_t)__float_as_int(E0.x) * HID + c);
                    float4 h1 = *reinterpret_cast<const float4*>(hsrc + (size_t)__float_as_int(E1.x) * HID + c);
                    float4 h2 = *reinterpret_cast<const float4*>(hsrc + (size_t)__float_as_int(E2.x) * HID + c);
                    float4 h3 = *reinterpret_cast<const float4*>(hsrc + (size_t)__float_as_int(E3.x) * HID + c);
#pragma unroll
                    for (int u = 0; u < 4; u++) {
                        float4 E = (u == 0) ? E0 : (u == 1) ? E1 : (u == 2) ? E2 : E3;
                        float4 hh = (u == 0) ? h0 : (u == 1) ? h1 : (u == 2) ? h2 : h3;
                        float hx = fmaxf(hh.x * sc4.x + sh4.x, 0.f);
                        float hy = fmaxf(hh.y * sc4.y + sh4.y, 0.f);
                        float hz = fmaxf(hh.z * sc4.z + sh4.z, 0.f);
                        float hw = fmaxf(hh.w * sc4.w + sh4.w, 0.f);
                        ax += fmaxf(hx + E.y * w0.x + E.z * w1.x + E.w * w2.x + b4.x, 0.f);
                        ay += fmaxf(hy + E.y * w0.y + E.z * w1.y + E.w * w2.y + b4.y, 0.f);
                        az += fmaxf(hz + E.y * w0.z + E.z * w1.z + E.w * w2.z + b4.z, 0.f);
                        aw += fmaxf(hw + E.y * w0.w + E.z * w1.w + E.w * w2.w + b4.w, 0.f);
                    }
                }
                for (; j < end; j++) {
                    float4 E = g_edge[j];
                    float4 hh = *reinterpret_cast<const float4*>(hsrc + (size_t)__float_as_int(E.x) * HID + c);
                    float hx = fmaxf(hh.x * sc4.x + sh4.x, 0.f);
                    float hy = fmaxf(hh.y * sc4.y + sh4.y, 0.f);
                    float hz = fmaxf(hh.z * sc4.z + sh4.z, 0.f);
                    float hw = fmaxf(hh.w * sc4.w + sh4.w, 0.f);
                    ax += fmaxf(hx + E.y * w0.x + E.z * w1.x + E.w * w2.x + b4.x, 0.f);
                    ay += fmaxf(hy + E.y * w0.y + E.z * w1.y + E.w * w2.y + b4.y, 0.f);
                    az += fmaxf(hz + E.y * w0.z + E.z * w1.z + E.w * w2.z + b4.z, 0.f);
                    aw += fmaxf(hw + E.y * w0.w + E.z * w1.w + E.w * w2.w + b4.w, 0.f);
                }
            }
            unsigned h01, l01, h23, l23;
            pk_split(ax, ay, h01, l01);
            pk_split(az, aw, h23, l23);
            unsigned* dh = reinterpret_cast<unsigned*>(Ahi + r * AROW + c);
            dh[0] = h01; dh[1] = h23;
            unsigned* dl = reinterpret_cast<unsigned*>(Alo + r * AROW + c);
            dl[0] = l01; dl[1] = l23;
        }
        __syncthreads();

        float acc[8][4];
        tensor_gemm(Ahi, Alo, wfhi1, wflo1, b1, warp, lane, acc);
        __syncthreads();                        // everyone done reading A
        store_T(Ahi, Alo, warp, lane, acc);     // overwrite A with relu(T)
        __syncthreads();
        tensor_gemm(Ahi, Alo, wfhi2, wflo2, b2, warp, lane, acc);
        epilogue(hdst, ssum, ssq, base, warp, lane, acc);
        __syncthreads();
        if (tid < HID) {
            atomicAdd(&g_stats[tid], ssum[tid]);
            atomicAdd(&g_stats[HID + tid], ssq[tid]);
        }
        __syncthreads();    // protect ssum/ssq and Ahi/Alo reuse across tiles
    }
}

// ------------------- FUSED node kernel, layer 1 (persistent, work-stealing) ----------
__global__ void __launch_bounds__(256, 3)
node1(const float* __restrict__ x, float* __restrict__ hout,
      const float* __restrict__ We, const float* __restrict__ be,
      const float* __restrict__ W11, const float* __restrict__ b1,
      const uint2* __restrict__ wfhi2, const uint2* __restrict__ wflo2, const float* __restrict__ b2) {
    extern __shared__ __align__(16) char smemc[];
    ushort_t* Thi = reinterpret_cast<ushort_t*>(smemc);
    ushort_t* Tlo = Thi + 64 * AROW;
    float* As7 = reinterpret_cast<float*>(Tlo + 64 * AROW);   // [64][8]
    float* sWe = As7 + 64 * 8;                                 // [3*7]
    float* sbe = sWe + 3 * IN_DIM;                             // [7]
    float* sW1 = sbe + IN_DIM;                                 // [7][128]
    float* ssum = sW1 + IN_DIM * HID;
    float* ssq = ssum + HID;
    __shared__ int s_tile;
    int tid = threadIdx.x;
    if (tid < 3 * IN_DIM) sWe[tid] = We[tid];
    if (tid >= 32 && tid < 32 + IN_DIM) sbe[tid - 32] = be[tid - 32];
    for (int i = tid; i < IN_DIM * HID; i += 256) sW1[i] = W11[i];
    __syncthreads();

    int warp = tid >> 5, lane = tid & 31;
    int mw = warp & 3, nh = warp >> 2;
    int grp = lane >> 2, qk = lane & 3;

    for (;;) {
        if (tid == 0) s_tile = atomicAdd(&g_tile[0], 1);
        __syncthreads();
        int tile = s_tile;
        if (tile >= NODE_TILES) return;
        int base = tile * 64;
        if (tid < HID) { ssum[tid] = 0.f; ssq[tid] = 0.f; }

        // ---- gather phase: 4 threads per node ----
        {
            int r = tid >> 2, sub = tid & 3;
            int n = base + r;
            float acc[IN_DIM];
#pragma unroll
            for (int k = 0; k < IN_DIM; k++) acc[k] = 0.f;
            if (n < N_NODES) {
                int beg = g_off[n], end = g_off[n + 1];
                for (int j = beg + sub; j < end; j += 4) {
                    float4 E = g_edge[j];
                    const float* x0 = x + (size_t)__float_as_int(E.x) * IN_DIM;
#pragma unroll
                    for (int k = 0; k < IN_DIM; k++) {
                        float m = x0[k] + E.y * sWe[k] + E.z * sWe[IN_DIM + k] + E.w * sWe[2 * IN_DIM + k] + sbe[k];
                        acc[k] += fmaxf(m, 0.f);
                    }
                }
            }
#pragma unroll
            for (int k = 0; k < IN_DIM; k++) {
                acc[k] += __shfl_xor_sync(0xffffffffu, acc[k], 1);
                acc[k] += __shfl_xor_sync(0xffffffffu, acc[k], 2);
            }
            if (sub == 0) {
                if (n < N_NODES) {
                    const float* xr = x + (size_t)n * IN_DIM;
#pragma unroll
                    for (int k = 0; k < IN_DIM; k++) As7[r * 8 + k] = xr[k] + acc[k];
                } else {
#pragma unroll
                    for (int k = 0; k < IN_DIM; k++) As7[r * 8 + k] = 0.f;
                }
                As7[r * 8 + 7] = 0.f;
            }
        }
        __syncthreads();

        float acc[8][4];
#pragma unroll
        for (int nt = 0; nt < 8; nt++) {
            int cc = nh * 64 + nt * 8 + qk * 2;
            float b0 = b1[cc], b1v = b1[cc + 1];
            acc[nt][0] = b0; acc[nt][1] = b1v; acc[nt][2] = b0; acc[nt][3] = b1v;
        }
        int r0l = mw * 16 + grp, r1l = r0l + 8;
#pragma unroll
        for (int k = 0; k < IN_DIM; k++) {
            float a0 = As7[r0l * 8 + k];
            float a1 = As7[r1l * 8 + k];
#pragma unroll
            for (int nt = 0; nt < 8; nt++) {
                int cc = nh * 64 + nt * 8 + qk * 2;
                float w0 = sW1[k * HID + cc], w1 = sW1[k * HID + cc + 1];
                acc[nt][0] += a0 * w0; acc[nt][1] += a0 * w1;
                acc[nt][2] += a1 * w0; acc[nt][3] += a1 * w1;
            }
        }
        store_T(Thi, Tlo, warp, lane, acc);
        __syncthreads();
        tensor_gemm(Thi, Tlo, wfhi2, wflo2, b2, warp, lane, acc);
        epilogue(hout, ssum, ssq, base, warp, lane, acc);
        __syncthreads();
        if (tid < HID) {
            atomicAdd(&g_stats[tid], ssum[tid]);
            atomicAdd(&g_stats[HID + tid], ssq[tid]);
        }
        __syncthreads();
    }
}

// ------------------- BN finalize; zeroes stats for next layer ----------
__global__ void bn_finalize(const float* __restrict__ gamma, const float* __restrict__ beta) {
    int t = threadIdx.x;
    float invN = 1.f / (float)N_NODES;
    float mu = g_stats[t] * invN;
    float var = g_stats[HID + t] * invN - mu * mu;
    float rs = rsqrtf(var + 1e-5f);
    float sc = gamma[t] * rs;
    g_scale[t] = sc;
    g_shift[t] = beta[t] - mu * sc;
    g_stats[t] = 0.f;
    g_stats[HID + t] = 0.f;
}

// ------------------- fused pool + head: block per graph, binary-search node range ----------
__global__ void head_kernel(const int* __restrict__ batch,
                            const float* __restrict__ Wf1, const float* __restrict__ bf1,
                            const float* __restrict__ Wf2, const float* __restrict__ bf2,
                            float* __restrict__ out) {
    __shared__ int lohi[2];
    __shared__ float p[HID];
    __shared__ float red[64];
    int g = blockIdx.x;
    int tid = threadIdx.x;   // 128 threads
    if (tid < 2) {
        int target = g + tid;        // lower_bound(batch, target)
        int lo = 0, hi = N_NODES;
        while (lo < hi) {
            int mid = (lo + hi) >> 1;
            if (batch[mid] < target) lo = mid + 1; else hi = mid;
        }
        lohi[tid] = lo;
    }
    __syncthreads();
    int lo = lohi[0], hi = lohi[1];
    float sc = g_scale[tid], sh = g_shift[tid];
    float s = 0.f;
    for (int n = lo; n < hi; n++)
        s += fmaxf(g_hpre[(size_t)n * HID + tid] * sc + sh, 0.f);
    int cnt = hi - lo;
    p[tid] = s / (float)(cnt > 0 ? cnt : 1);
    __syncthreads();
    if (tid < 64) {
        float acc = bf1[tid];
        for (int k = 0; k < HID; k++) acc += p[k] * Wf1[k * 64 + tid];
        red[tid] = fmaxf(acc, 0.f) * Wf2[tid];
    }
    __syncthreads();
    for (int st = 32; st > 0; st >>= 1) {
        if (tid < st) red[tid] += red[tid + st];
        __syncthreads();
    }
    if (tid == 0) out[g] = red[0] + bf2[0];
}

// ------------------- launch -------------------
extern "C" void kernel_launch(void* const* d_in, const int* in_sizes, int n_in,
                              void* d_out, int out_size) {
    const float* x = (const float*)d_in[0];
    const float* ea = (const float*)d_in[1];
    const int* ei = (const int*)d_in[2];
    const int* batch = (const int*)d_in[3];
    const float* We1 = (const float*)d_in[4];  const float* be1 = (const float*)d_in[5];
    const float* W11 = (const float*)d_in[6];  const float* b11 = (const float*)d_in[7];
    const float* W12 = (const float*)d_in[8];  const float* b12 = (const float*)d_in[9];
    const float* gm1 = (const float*)d_in[10]; const float* bt1 = (const float*)d_in[11];
    const float* We2 = (const float*)d_in[12]; const float* be2 = (const float*)d_in[13];
    const float* W21 = (const float*)d_in[14]; const float* b21 = (const float*)d_in[15];
    const float* W22 = (const float*)d_in[16]; const float* b22 = (const float*)d_in[17];
    const float* gm2 = (const float*)d_in[18]; const float* bt2 = (const float*)d_in[19];
    const float* We3 = (const float*)d_in[20]; const float* be3 = (const float*)d_in[21];
    const float* W31 = (const float*)d_in[22]; const float* b31 = (const float*)d_in[23];
    const float* W32 = (const float*)d_in[24]; const float* b32 = (const float*)d_in[25];
    const float* gm3 = (const float*)d_in[26]; const float* bt3 = (const float*)d_in[27];
    const float* Wf1 = (const float*)d_in[28]; const float* bf1 = (const float*)d_in[29];
    const float* Wf2 = (const float*)d_in[30]; const float* bf2 = (const float*)d_in[31];
    float* out = (float*)d_out;

    float *p_hpre, *p_hpre2;
    cudaGetSymbolAddress((void**)&p_hpre, g_hpre);
    cudaGetSymbolAddress((void**)&p_hpre2, g_hpre2);
    uint2 *p_wfhi, *p_wflo;
    cudaGetSymbolAddress((void**)&p_wfhi, g_wfhi);
    cudaGetSymbolAddress((void**)&p_wflo, g_wflo);

    const int SMEM_T = 2 * 64 * AROW * 2 + 2 * HID * 4;   // ~35.8KB
    const int SMEM_1 = 2 * 64 * AROW * 2 +
                       (64 * 8 + 3 * IN_DIM + IN_DIM + IN_DIM * HID + 2 * HID) * 4;  // ~41.6KB
    cudaFuncSetAttribute((const void*)node_fused, cudaFuncAttributeMaxDynamicSharedMemorySize, SMEM_T);
    cudaFuncSetAttribute((const void*)node1, cudaFuncAttributeMaxDynamicSharedMemorySize, SMEM_1);

    // ---------- init + CSC build ----------
    prep_wfrag<<<dim3(16, 5), 256>>>(W12, W21, W22, W31, W32);
    zero_misc<<<(N_NODES + 255) / 256, 256>>>();
    csr_hist<<<(N_EDGES + 255) / 256, 256>>>(ei);
    scan1<<<NSCB, SCB>>>();
    scan3<<<(N_NODES + 255) / 256, 256>>>();
    csr_scatter<<<(N_EDGES + 255) / 256, 256>>>(ei, ea);

    // ---------- layer 1 (fully fused, persistent) ----------
    node1<<<PERSIST_BLOCKS, 256, SMEM_1>>>(x, p_hpre, We1, be1, W11, b11,
                                           p_wfhi + 0 * 4096, p_wflo + 0 * 4096, b12);
    bn_finalize<<<1, HID>>>(gm1, bt1);

    // ---------- layer 2 (fused gather + MLP; hpre -> hpre2) ----------
    node_fused<<<PERSIST_BLOCKS, 256, SMEM_T>>>(p_hpre, p_hpre2, 1, We2, be2,
                                                p_wfhi + 1 * 4096, p_wflo + 1 * 4096, b21,
                                                p_wfhi + 2 * 4096, p_wflo + 2 * 4096, b22);
    bn_finalize<<<1, HID>>>(gm2, bt2);

    // ---------- layer 3 (fused; hpre2 -> hpre) ----------
    node_fused<<<PERSIST_BLOCKS, 256, SMEM_T>>>(p_hpre2, p_hpre, 2, We3, be3,
                                                p_wfhi + 3 * 4096, p_wflo + 3 * 4096, b31,
                                                p_wfhi + 4 * 4096, p_wflo + 4 * 4096, b32);
    bn_finalize<<<1, HID>>>(gm3, bt3);

    // ---------- fused pool + head ----------
    head_kernel<<<N_GRAPHS, HID>>>(batch, Wf1, bf1, Wf2, bf2, out);
}

// round 15
// speedup vs baseline: 1.0579x; 1.0579x over previous
#include <cuda_runtime.h>
#include <cuda_bf16.h>
#include <cstdio>

#define N_NODES 50000
#define N_EDGES 800000
#define N_GRAPHS 2048
#define HID 128
#define IN_DIM 7
#define SCB 1024
#define NSCB ((N_NODES + SCB - 1) / SCB)   // 49

typedef unsigned short ushort_t;

// ------------------- scratch (device globals; no allocation) -------------------
__device__ float g_hpre[N_NODES * HID];          // pre-BN features (buffer A)
__device__ float g_hpre2[N_NODES * HID];         // pre-BN features (buffer B)
__device__ float g_stats[2 * HID];
__device__ float g_scale[HID];
__device__ float g_shift[HID];
// CSC (edges grouped by dst): sorted edge records {src_bits, ea0, ea1, ea2}
__device__ int g_cnti[N_NODES];
__device__ int g_off[N_NODES + 1];
__device__ int g_fill[N_NODES];
__device__ float4 g_edge[N_EDGES];
__device__ int g_bsum[64];
// weight fragments: 5 matrices (W12,W21,W22,W31,W32), [nt16][ks8][lane32] uint2
__device__ uint2 g_wfhi[5 * 4096];
__device__ uint2 g_wflo[5 * 4096];

__device__ __forceinline__ void mma16816(float acc[4],
                                         unsigned a0, unsigned a1, unsigned a2, unsigned a3,
                                         unsigned b0, unsigned b1) {
    asm volatile("mma.sync.aligned.m16n8k16.row.col.f32.bf16.bf16.f32 "
                 "{%0,%1,%2,%3},{%4,%5,%6,%7},{%8,%9},{%0,%1,%2,%3};"
                 : "+f"(acc[0]), "+f"(acc[1]), "+f"(acc[2]), "+f"(acc[3])
                 : "r"(a0), "r"(a1), "r"(a2), "r"(a3), "r"(b0), "r"(b1));
}

__device__ __forceinline__ void pk_split(float a, float b, unsigned& hi, unsigned& lo) {
    __nv_bfloat16 ha = __float2bfloat16(a);
    __nv_bfloat16 hb = __float2bfloat16(b);
    __nv_bfloat16 la = __float2bfloat16(a - __bfloat162float(ha));
    __nv_bfloat16 lb = __float2bfloat16(b - __bfloat162float(hb));
    hi = (unsigned)__bfloat16_as_ushort(ha) | ((unsigned)__bfloat16_as_ushort(hb) << 16);
    lo = (unsigned)__bfloat16_as_ushort(la) | ((unsigned)__bfloat16_as_ushort(lb) << 16);
}

// ------------------- weight fragment prep -------------------
__global__ void prep_wfrag(const float* W12, const float* W21, const float* W22,
                           const float* W31, const float* W32) {
    const float* Ws[5] = {W12, W21, W22, W31, W32};
    int m = blockIdx.y;
    const float* W = Ws[m];
    int idx = blockIdx.x * 256 + threadIdx.x;
    int lane = idx & 31, ks = (idx >> 5) & 7, nt = idx >> 8;
    int n = nt * 8 + (lane >> 2);
    int k0 = ks * 16 + (lane & 3) * 2;
    unsigned h0, l0, h1, l1;
    pk_split(W[k0 * HID + n], W[(k0 + 1) * HID + n], h0, l0);
    pk_split(W[(k0 + 8) * HID + n], W[(k0 + 9) * HID + n], h1, l1);
    g_wfhi[m * 4096 + idx] = make_uint2(h0, h1);
    g_wflo[m * 4096 + idx] = make_uint2(l0, l1);
}

// ------------------- utility -------------------
__global__ void zero_misc() {
    int i = blockIdx.x * blockDim.x + threadIdx.x;
    if (i < 2 * HID) g_stats[i] = 0.f;
    if (i < N_NODES) g_cnti[i] = 0;
}

// ------------------- CSC build -------------------
__global__ void csr_hist(const int* __restrict__ ei) {
    int e = blockIdx.x * blockDim.x + threadIdx.x;
    if (e < N_EDGES) atomicAdd(&g_cnti[ei[N_EDGES + e]], 1);
}

__global__ void scan1() {
    __shared__ int warpsum[32];
    int i = blockIdx.x * SCB + threadIdx.x;
    int lane = threadIdx.x & 31, wid = threadIdx.x >> 5;
    int v = (i < N_NODES) ? g_cnti[i] : 0;
    int s = v;
#pragma unroll
    for (int o = 1; o < 32; o <<= 1) {
        int t = __shfl_up_sync(0xffffffffu, s, o);
        if (lane >= o) s += t;
    }
    if (lane == 31) warpsum[wid] = s;
    __syncthreads();
    if (wid == 0) {
        int ws = warpsum[lane];
#pragma unroll
        for (int o = 1; o < 32; o <<= 1) {
            int t = __shfl_up_sync(0xffffffffu, ws, o);
            if (lane >= o) ws += t;
        }
        warpsum[lane] = ws;
    }
    __syncthreads();
    int total = s + (wid > 0 ? warpsum[wid - 1] : 0);
    if (i < N_NODES) g_off[i] = total - v;   // exclusive within block
    if (threadIdx.x == SCB - 1) g_bsum[blockIdx.x] = total;
}

// scan3 with scan2 merged: each block prefix-sums the 49 block sums locally.
__global__ void scan3() {
    __shared__ int bs[64];
    int tid = threadIdx.x;
    if (tid < 64) bs[tid] = (tid < NSCB) ? g_bsum[tid] : 0;
    __syncthreads();
    for (int o = 1; o < 64; o <<= 1) {
        int t = (tid < 64 && tid >= o) ? bs[tid - o] : 0;
        __syncthreads();
        if (tid < 64) bs[tid] += t;
        __syncthreads();
    }
    int i = blockIdx.x * blockDim.x + tid;
    if (i < N_NODES) {
        int blk = i / SCB;
        int pre = (blk > 0) ? bs[blk - 1] : 0;
        int o = g_off[i] + pre;
        g_off[i] = o;
        g_fill[i] = o;
    }
    if (i == 0) g_off[N_NODES] = N_EDGES;
}

// scatter sorted edge records: one float4 per edge {src_bits, ea0, ea1, ea2}
__global__ void csr_scatter(const int* __restrict__ ei, const float* __restrict__ ea) {
    int e = blockIdx.x * blockDim.x + threadIdx.x;
    if (e < N_EDGES) {
        int d = ei[N_EDGES + e];
        int s = ei[e];
        float a0 = ea[e * 3], a1 = ea[e * 3 + 1], a2 = ea[e * 3 + 2];
        int p = atomicAdd(&g_fill[d], 1);
        g_edge[p] = make_float4(__int_as_float(s), a0, a1, a2);
    }
}

// ------------------- tensor GEMM core pieces -------------------
#define AROW 136

__device__ __forceinline__ void tensor_gemm(const ushort_t* Ahi, const ushort_t* Alo,
                                            const uint2* __restrict__ wfhi,
                                            const uint2* __restrict__ wflo,
                                            const float* __restrict__ bias,
                                            int warp, int lane, float acc[8][4]) {
    int mw = warp & 3, nh = warp >> 2;
    int grp = lane >> 2, qk = lane & 3;
#pragma unroll
    for (int nt = 0; nt < 8; nt++) {
        int cc = nh * 64 + nt * 8 + qk * 2;
        float b0 = bias[cc], b1v = bias[cc + 1];
        acc[nt][0] = b0; acc[nt][1] = b1v; acc[nt][2] = b0; acc[nt][3] = b1v;
    }
    int arow = (mw * 16 + grp) * AROW;
#pragma unroll 2
    for (int ks = 0; ks < 8; ks++) {
        int ab = arow + ks * 16 + qk * 2;
        unsigned ah0 = *reinterpret_cast<const unsigned*>(Ahi + ab);
        unsigned ah1 = *reinterpret_cast<const unsigned*>(Ahi + ab + 8 * AROW);
        unsigned ah2 = *reinterpret_cast<const unsigned*>(Ahi + ab + 8);
        unsigned ah3 = *reinterpret_cast<const unsigned*>(Ahi + ab + 8 * AROW + 8);
        unsigned al0 = *reinterpret_cast<const unsigned*>(Alo + ab);
        unsigned al1 = *reinterpret_cast<const unsigned*>(Alo + ab + 8 * AROW);
        unsigned al2 = *reinterpret_cast<const unsigned*>(Alo + ab + 8);
        unsigned al3 = *reinterpret_cast<const unsigned*>(Alo + ab + 8 * AROW + 8);
        const uint2* ph = wfhi + ((nh * 8) * 8 + ks) * 32 + lane;
        const uint2* pl = wflo + ((nh * 8) * 8 + ks) * 32 + lane;
#pragma unroll
        for (int nt = 0; nt < 8; nt++) {
            uint2 bh = ph[nt * 256];
            uint2 bl = pl[nt * 256];
            mma16816(acc[nt], ah0, ah1, ah2, ah3, bh.x, bh.y);
            mma16816(acc[nt], ah0, ah1, ah2, ah3, bl.x, bl.y);
            mma16816(acc[nt], al0, al1, al2, al3, bh.x, bh.y);
        }
    }
}

// relu + bf16-split + store acc into (reused) A smem
__device__ __forceinline__ void store_T(ushort_t* Thi, ushort_t* Tlo,
                                        int warp, int lane, float acc[8][4]) {
    int mw = warp & 3, nh = warp >> 2;
    int grp = lane >> 2, qk = lane & 3;
    int r0 = (mw * 16 + grp) * AROW, r1 = r0 + 8 * AROW;
#pragma unroll
    for (int nt = 0; nt < 8; nt++) {
        int cc = nh * 64 + nt * 8 + qk * 2;
        unsigned hi, lo;
        pk_split(fmaxf(acc[nt][0], 0.f), fmaxf(acc[nt][1], 0.f), hi, lo);
        *reinterpret_cast<unsigned*>(Thi + r0 + cc) = hi;
        *reinterpret_cast<unsigned*>(Tlo + r0 + cc) = lo;
        pk_split(fmaxf(acc[nt][2], 0.f), fmaxf(acc[nt][3], 0.f), hi, lo);
        *reinterpret_cast<unsigned*>(Thi + r1 + cc) = hi;
        *reinterpret_cast<unsigned*>(Tlo + r1 + cc) = lo;
    }
}

__device__ __forceinline__ void epilogue(float* __restrict__ hout,
                                         float* ssum, float* ssq, int base,
                                         int warp, int lane, float acc[8][4]) {
    int mw = warp & 3, nh = warp >> 2;
    int grp = lane >> 2, qk = lane & 3;
    int r0 = base + mw * 16 + grp, r1 = r0 + 8;
    bool v0 = r0 < N_NODES, v1 = r1 < N_NODES;
#pragma unroll
    for (int nt = 0; nt < 8; nt++) {
        int cc = nh * 64 + nt * 8 + qk * 2;
        float f0 = acc[nt][0], f1 = acc[nt][1], f2 = acc[nt][2], f3 = acc[nt][3];
        if (v0) *reinterpret_cast<float2*>(hout + (size_t)r0 * HID + cc) = make_float2(f0, f1);
        if (v1) *reinterpret_cast<float2*>(hout + (size_t)r1 * HID + cc) = make_float2(f2, f3);
        float s0 = (v0 ? f0 : 0.f) + (v1 ? f2 : 0.f);
        float s1 = (v0 ? f1 : 0.f) + (v1 ? f3 : 0.f);
        float q0 = (v0 ? f0 * f0 : 0.f) + (v1 ? f2 * f2 : 0.f);
        float q1 = (v0 ? f1 * f1 : 0.f) + (v1 ? f3 * f3 : 0.f);
        atomicAdd(&ssum[cc], s0);
        atomicAdd(&ssum[cc + 1], s1);
        atomicAdd(&ssq[cc], q0);
        atomicAdd(&ssq[cc + 1], q1);
    }
}

// ------------------- FUSED node kernel, layers 2/3 (3 blocks/SM — register-optimal) ----------
__global__ void __launch_bounds__(256, 3)
node_fused(const float* __restrict__ hsrc, float* __restrict__ hdst,
           const float* __restrict__ We, const float* __restrict__ be,
           const uint2* __restrict__ wfhi1, const uint2* __restrict__ wflo1, const float* __restrict__ b1,
           const uint2* __restrict__ wfhi2, const uint2* __restrict__ wflo2, const float* __restrict__ b2) {
    extern __shared__ __align__(16) char smemc[];
    ushort_t* Ahi = reinterpret_cast<ushort_t*>(smemc);
    ushort_t* Alo = Ahi + 64 * AROW;
    float* ssum = reinterpret_cast<float*>(Alo + 64 * AROW);
    float* ssq = ssum + HID;
    int tid = threadIdx.x;
    int base = blockIdx.x * 64;
    if (tid < HID) { ssum[tid] = 0.f; ssq[tid] = 0.f; }

    int warp = tid >> 5, lane = tid & 31;
    int c = lane * 4;
    {
        float4 w0 = *reinterpret_cast<const float4*>(We + c);
        float4 w1 = *reinterpret_cast<const float4*>(We + HID + c);
        float4 w2 = *reinterpret_cast<const float4*>(We + 2 * HID + c);
        float4 b4 = *reinterpret_cast<const float4*>(be + c);
        float4 sc4 = *reinterpret_cast<const float4*>(g_scale + c);
        float4 sh4 = *reinterpret_cast<const float4*>(g_shift + c);

        for (int rr = 0; rr < 8; rr++) {
            int r = warp * 8 + rr;
            int n = base + r;
            float ax = 0.f, ay = 0.f, az = 0.f, aw = 0.f;
            if (n < N_NODES) {
                float4 own = *reinterpret_cast<const float4*>(hsrc + (size_t)n * HID + c);
                ax = fmaxf(own.x * sc4.x + sh4.x, 0.f);
                ay = fmaxf(own.y * sc4.y + sh4.y, 0.f);
                az = fmaxf(own.z * sc4.z + sh4.z, 0.f);
                aw = fmaxf(own.w * sc4.w + sh4.w, 0.f);
                int beg = g_off[n], end = g_off[n + 1];
                int j = beg;
                for (; j + 4 <= end; j += 4) {
                    float4 E0 = g_edge[j], E1 = g_edge[j + 1], E2 = g_edge[j + 2], E3 = g_edge[j + 3];
                    float4 h0 = *reinterpret_cast<const float4*>(hsrc + (size_t)__float_as_int(E0.x) * HID + c);
                    float4 h1 = *reinterpret_cast<const float4*>(hsrc + (size_t)__float_as_int(E1.x) * HID + c);
                    float4 h2 = *reinterpret_cast<const float4*>(hsrc + (size_t)__float_as_int(E2.x) * HID + c);
                    float4 h3 = *reinterpret_cast<const float4*>(hsrc + (size_t)__float_as_int(E3.x) * HID + c);
#pragma unroll
                    for (int u = 0; u < 4; u++) {
                        float4 E = (u == 0) ? E0 : (u == 1) ? E1 : (u == 2) ? E2 : E3;
                        float4 hh = (u == 0) ? h0 : (u == 1) ? h1 : (u == 2) ? h2 : h3;
                        float hx = fmaxf(hh.x * sc4.x + sh4.x, 0.f);
                        float hy = fmaxf(hh.y * sc4.y + sh4.y, 0.f);
                        float hz = fmaxf(hh.z * sc4.z + sh4.z, 0.f);
                        float hw = fmaxf(hh.w * sc4.w + sh4.w, 0.f);
                        ax += fmaxf(hx + E.y * w0.x + E.z * w1.x + E.w * w2.x + b4.x, 0.f);
                        ay += fmaxf(hy + E.y * w0.y + E.z * w1.y + E.w * w2.y + b4.y, 0.f);
                        az += fmaxf(hz + E.y * w0.z + E.z * w1.z + E.w * w2.z + b4.z, 0.f);
                        aw += fmaxf(hw + E.y * w0.w + E.z * w1.w + E.w * w2.w + b4.w, 0.f);
                    }
                }
                for (; j < end; j++) {
                    float4 E = g_edge[j];
                    float4 hh = *reinterpret_cast<const float4*>(hsrc + (size_t)__float_as_int(E.x) * HID + c);
                    float hx = fmaxf(hh.x * sc4.x + sh4.x, 0.f);
                    float hy = fmaxf(hh.y * sc4.y + sh4.y, 0.f);
                    float hz = fmaxf(hh.z * sc4.z + sh4.z, 0.f);
                    float hw = fmaxf(hh.w * sc4.w + sh4.w, 0.f);
                    ax += fmaxf(hx + E.y * w0.x + E.z * w1.x + E.w * w2.x + b4.x, 0.f);
                    ay += fmaxf(hy + E.y * w0.y + E.z * w1.y + E.w * w2.y + b4.y, 0.f);
                    az += fmaxf(hz + E.y * w0.z + E.z * w1.z + E.w * w2.z + b4.z, 0.f);
                    aw += fmaxf(hw + E.y * w0.w + E.z * w1.w + E.w * w2.w + b4.w, 0.f);
                }
            }
            unsigned h01, l01, h23, l23;
            pk_split(ax, ay, h01, l01);
            pk_split(az, aw, h23, l23);
            unsigned* dh = reinterpret_cast<unsigned*>(Ahi + r * AROW + c);
            dh[0] = h01; dh[1] = h23;
            unsigned* dl = reinterpret_cast<unsigned*>(Alo + r * AROW + c);
            dl[0] = l01; dl[1] = l23;
        }
    }
    __syncthreads();

    float acc[8][4];
    tensor_gemm(Ahi, Alo, wfhi1, wflo1, b1, warp, lane, acc);
    __syncthreads();                        // everyone done reading A
    store_T(Ahi, Alo, warp, lane, acc);     // overwrite A with relu(T)
    __syncthreads();
    tensor_gemm(Ahi, Alo, wfhi2, wflo2, b2, warp, lane, acc);
    epilogue(hdst, ssum, ssq, base, warp, lane, acc);
    __syncthreads();
    if (tid < HID) {
        atomicAdd(&g_stats[tid], ssum[tid]);
        atomicAdd(&g_stats[HID + tid], ssq[tid]);
    }
}

// ------------------- FUSED node kernel, layer 1 (gather7 + scalar GEMM1 + tensor GEMM2) ----------
__global__ void __launch_bounds__(256, 3)
node1(const float* __restrict__ x, float* __restrict__ hout,
      const float* __restrict__ We, const float* __restrict__ be,
      const float* __restrict__ W11, const float* __restrict__ b1,
      const uint2* __restrict__ wfhi2, const uint2* __restrict__ wflo2, const float* __restrict__ b2) {
    extern __shared__ __align__(16) char smemc[];
    ushort_t* Thi = reinterpret_cast<ushort_t*>(smemc);
    ushort_t* Tlo = Thi + 64 * AROW;
    float* As7 = reinterpret_cast<float*>(Tlo + 64 * AROW);   // [64][8]
    float* sWe = As7 + 64 * 8;                                 // [3*7]
    float* sbe = sWe + 3 * IN_DIM;                             // [7]
    float* sW1 = sbe + IN_DIM;                                 // [7][128]
    float* ssum = sW1 + IN_DIM * HID;
    float* ssq = ssum + HID;
    int tid = threadIdx.x;
    int base = blockIdx.x * 64;
    if (tid < HID) { ssum[tid] = 0.f; ssq[tid] = 0.f; }
    if (tid < 3 * IN_DIM) sWe[tid] = We[tid];
    if (tid >= 32 && tid < 32 + IN_DIM) sbe[tid - 32] = be[tid - 32];
    for (int i = tid; i < IN_DIM * HID; i += 256) sW1[i] = W11[i];
    __syncthreads();

    // ---- gather phase: 4 threads per node ----
    {
        int r = tid >> 2, sub = tid & 3;
        int n = base + r;
        float acc[IN_DIM];
#pragma unroll
        for (int k = 0; k < IN_DIM; k++) acc[k] = 0.f;
        if (n < N_NODES) {
            int beg = g_off[n], end = g_off[n + 1];
            for (int j = beg + sub; j < end; j += 4) {
                float4 E = g_edge[j];
                const float* x0 = x + (size_t)__float_as_int(E.x) * IN_DIM;
#pragma unroll
                for (int k = 0; k < IN_DIM; k++) {
                    float m = x0[k] + E.y * sWe[k] + E.z * sWe[IN_DIM + k] + E.w * sWe[2 * IN_DIM + k] + sbe[k];
                    acc[k] += fmaxf(m, 0.f);
                }
            }
        }
#pragma unroll
        for (int k = 0; k < IN_DIM; k++) {
            acc[k] += __shfl_xor_sync(0xffffffffu, acc[k], 1);
            acc[k] += __shfl_xor_sync(0xffffffffu, acc[k], 2);
        }
        if (sub == 0) {
            if (n < N_NODES) {
                const float* xr = x + (size_t)n * IN_DIM;
#pragma unroll
                for (int k = 0; k < IN_DIM; k++) As7[r * 8 + k] = xr[k] + acc[k];
            } else {
#pragma unroll
                for (int k = 0; k < IN_DIM; k++) As7[r * 8 + k] = 0.f;
            }
            As7[r * 8 + 7] = 0.f;
        }
    }
    __syncthreads();

    int warp = tid >> 5, lane = tid & 31;
    int mw = warp & 3, nh = warp >> 2;
    int grp = lane >> 2, qk = lane & 3;
    float acc[8][4];
#pragma unroll
    for (int nt = 0; nt < 8; nt++) {
        int cc = nh * 64 + nt * 8 + qk * 2;
        float b0 = b1[cc], b1v = b1[cc + 1];
        acc[nt][0] = b0; acc[nt][1] = b1v; acc[nt][2] = b0; acc[nt][3] = b1v;
    }
    int r0l = mw * 16 + grp, r1l = r0l + 8;
#pragma unroll
    for (int k = 0; k < IN_DIM; k++) {
        float a0 = As7[r0l * 8 + k];
        float a1 = As7[r1l * 8 + k];
#pragma unroll
        for (int nt = 0; nt < 8; nt++) {
            int cc = nh * 64 + nt * 8 + qk * 2;
            float w0 = sW1[k * HID + cc], w1 = sW1[k * HID + cc + 1];
            acc[nt][0] += a0 * w0; acc[nt][1] += a0 * w1;
            acc[nt][2] += a1 * w0; acc[nt][3] += a1 * w1;
        }
    }
    store_T(Thi, Tlo, warp, lane, acc);
    __syncthreads();
    tensor_gemm(Thi, Tlo, wfhi2, wflo2, b2, warp, lane, acc);
    epilogue(hout, ssum, ssq, base, warp, lane, acc);
    __syncthreads();
    if (tid < HID) {
        atomicAdd(&g_stats[tid], ssum[tid]);
        atomicAdd(&g_stats[HID + tid], ssq[tid]);
    }
}

// ------------------- BN finalize; zeroes stats for next layer ----------
__global__ void bn_finalize(const float* __restrict__ gamma, const float* __restrict__ beta) {
    int t = threadIdx.x;
    float invN = 1.f / (float)N_NODES;
    float mu = g_stats[t] * invN;
    float var = g_stats[HID + t] * invN - mu * mu;
    float rs = rsqrtf(var + 1e-5f);
    float sc = gamma[t] * rs;
    g_scale[t] = sc;
    g_shift[t] = beta[t] - mu * sc;
    g_stats[t] = 0.f;
    g_stats[HID + t] = 0.f;
}

// ------------------- fused pool + head: block per graph, binary-search node range ----------
__global__ void head_kernel(const int* __restrict__ batch,
                            const float* __restrict__ Wf1, const float* __restrict__ bf1,
                            const float* __restrict__ Wf2, const float* __restrict__ bf2,
                            float* __restrict__ out) {
    __shared__ int lohi[2];
    __shared__ float p[HID];
    __shared__ float red[64];
    int g = blockIdx.x;
    int tid = threadIdx.x;   // 128 threads
    if (tid < 2) {
        int target = g + tid;        // lower_bound(batch, target)
        int lo = 0, hi = N_NODES;
        while (lo < hi) {
            int mid = (lo + hi) >> 1;
            if (batch[mid] < target) lo = mid + 1; else hi = mid;
        }
        lohi[tid] = lo;
    }
    __syncthreads();
    int lo = lohi[0], hi = lohi[1];
    float sc = g_scale[tid], sh = g_shift[tid];
    float s = 0.f;
    for (int n = lo; n < hi; n++)
        s += fmaxf(g_hpre[(size_t)n * HID + tid] * sc + sh, 0.f);
    int cnt = hi - lo;
    p[tid] = s / (float)(cnt > 0 ? cnt : 1);
    __syncthreads();
    if (tid < 64) {
        float acc = bf1[tid];
        for (int k = 0; k < HID; k++) acc += p[k] * Wf1[k * 64 + tid];
        red[tid] = fmaxf(acc, 0.f) * Wf2[tid];
    }
    __syncthreads();
    for (int st = 32; st > 0; st >>= 1) {
        if (tid < st) red[tid] += red[tid + st];
        __syncthreads();
    }
    if (tid == 0) out[g] = red[0] + bf2[0];
}

// ------------------- launch -------------------
extern "C" void kernel_launch(void* const* d_in, const int* in_sizes, int n_in,
                              void* d_out, int out_size) {
    const float* x = (const float*)d_in[0];
    const float* ea = (const float*)d_in[1];
    const int* ei = (const int*)d_in[2];
    const int* batch = (const int*)d_in[3];
    const float* We1 = (const float*)d_in[4];  const float* be1 = (const float*)d_in[5];
    const float* W11 = (const float*)d_in[6];  const float* b11 = (const float*)d_in[7];
    const float* W12 = (const float*)d_in[8];  const float* b12 = (const float*)d_in[9];
    const float* gm1 = (const float*)d_in[10]; const float* bt1 = (const float*)d_in[11];
    const float* We2 = (const float*)d_in[12]; const float* be2 = (const float*)d_in[13];
    const float* W21 = (const float*)d_in[14]; const float* b21 = (const float*)d_in[15];
    const float* W22 = (const float*)d_in[16]; const float* b22 = (const float*)d_in[17];
    const float* gm2 = (const float*)d_in[18]; const float* bt2 = (const float*)d_in[19];
    const float* We3 = (const float*)d_in[20]; const float* be3 = (const float*)d_in[21];
    const float* W31 = (const float*)d_in[22]; const float* b31 = (const float*)d_in[23];
    const float* W32 = (const float*)d_in[24]; const float* b32 = (const float*)d_in[25];
    const float* gm3 = (const float*)d_in[26]; const float* bt3 = (const float*)d_in[27];
    const float* Wf1 = (const float*)d_in[28]; const float* bf1 = (const float*)d_in[29];
    const float* Wf2 = (const float*)d_in[30]; const float* bf2 = (const float*)d_in[31];
    float* out = (float*)d_out;

    float *p_hpre, *p_hpre2;
    cudaGetSymbolAddress((void**)&p_hpre, g_hpre);
    cudaGetSymbolAddress((void**)&p_hpre2, g_hpre2);
    uint2 *p_wfhi, *p_wflo;
    cudaGetSymbolAddress((void**)&p_wfhi, g_wfhi);
    cudaGetSymbolAddress((void**)&p_wflo, g_wflo);

    const int SMEM_T = 2 * 64 * AROW * 2 + 2 * HID * 4;   // ~35.8KB
    const int SMEM_1 = 2 * 64 * AROW * 2 +
                       (64 * 8 + 3 * IN_DIM + IN_DIM + IN_DIM * HID + 2 * HID) * 4;  // ~41.6KB
    cudaFuncSetAttribute((const void*)node_fused, cudaFuncAttributeMaxDynamicSharedMemorySize, SMEM_T);
    cudaFuncSetAttribute((const void*)node1, cudaFuncAttributeMaxDynamicSharedMemorySize, SMEM_1);

    const int nodeBlocks = (N_NODES + 63) / 64;

    // ---------- init + CSC build ----------
    prep_wfrag<<<dim3(16, 5), 256>>>(W12, W21, W22, W31, W32);
    zero_misc<<<(N_NODES + 255) / 256, 256>>>();
    csr_hist<<<(N_EDGES + 255) / 256, 256>>>(ei);
    scan1<<<NSCB, SCB>>>();
    scan3<<<(N_NODES + 255) / 256, 256>>>();
    csr_scatter<<<(N_EDGES + 255) / 256, 256>>>(ei, ea);

    // ---------- layer 1 (fully fused) ----------
    node1<<<nodeBlocks, 256, SMEM_1>>>(x, p_hpre, We1, be1, W11, b11,
                                       p_wfhi + 0 * 4096, p_wflo + 0 * 4096, b12);
    bn_finalize<<<1, HID>>>(gm1, bt1);

    // ---------- layer 2 (fused gather + MLP; hpre -> hpre2) ----------
    node_fused<<<nodeBlocks, 256, SMEM_T>>>(p_hpre, p_hpre2, We2, be2,
                                            p_wfhi + 1 * 4096, p_wflo + 1 * 4096, b21,
                                            p_wfhi + 2 * 4096, p_wflo + 2 * 4096, b22);
    bn_finalize<<<1, HID>>>(gm2, bt2);

    // ---------- layer 3 (fused; hpre2 -> hpre) ----------
    node_fused<<<nodeBlocks, 256, SMEM_T>>>(p_hpre2, p_hpre, We3, be3,
                                            p_wfhi + 3 * 4096, p_wflo + 3 * 4096, b31,
                                            p_wfhi + 4 * 4096, p_wflo + 4 * 4096, b32);
    bn_finalize<<<1, HID>>>(gm3, bt3);

    // ---------- fused pool + head ----------
    head_kernel<<<N_GRAPHS, HID>>>(batch, Wf1, bf1, Wf2, bf2, out);
}

// round 16
// speedup vs baseline: 1.0931x; 1.0333x over previous
#include <cuda_runtime.h>
#include <cuda_bf16.h>
#include <cstdio>

#define N_NODES 50000
#define N_EDGES 800000
#define N_GRAPHS 2048
#define HID 128
#define IN_DIM 7
#define SCB 1024
#define NSCB ((N_NODES + SCB - 1) / SCB)   // 49

typedef unsigned short ushort_t;

// ------------------- scratch (device globals; no allocation) -------------------
__device__ float g_hpre[N_NODES * HID];          // pre-BN features (buffer A)
__device__ float g_hpre2[N_NODES * HID];         // pre-BN features (buffer B)
__device__ float g_stats[2 * HID];
__device__ float g_scale[HID];
__device__ float g_shift[HID];
// CSC (edges grouped by dst): sorted edge records {src_bits, ea0, ea1, ea2}
__device__ int g_cnti[N_NODES];
__device__ int g_off[N_NODES + 1];
__device__ int g_fill[N_NODES];
__device__ float4 g_edge[N_EDGES];
__device__ int g_bsum[64];
// weight fragments: 5 matrices (W12,W21,W22,W31,W32), [nt16][ks8][lane32] uint2
__device__ uint2 g_wfhi[5 * 4096];
__device__ uint2 g_wflo[5 * 4096];

__device__ __forceinline__ void mma16816(float acc[4],
                                         unsigned a0, unsigned a1, unsigned a2, unsigned a3,
                                         unsigned b0, unsigned b1) {
    asm volatile("mma.sync.aligned.m16n8k16.row.col.f32.bf16.bf16.f32 "
                 "{%0,%1,%2,%3},{%4,%5,%6,%7},{%8,%9},{%0,%1,%2,%3};"
                 : "+f"(acc[0]), "+f"(acc[1]), "+f"(acc[2]), "+f"(acc[3])
                 : "r"(a0), "r"(a1), "r"(a2), "r"(a3), "r"(b0), "r"(b1));
}

__device__ __forceinline__ void pk_split(float a, float b, unsigned& hi, unsigned& lo) {
    __nv_bfloat16 ha = __float2bfloat16(a);
    __nv_bfloat16 hb = __float2bfloat16(b);
    __nv_bfloat16 la = __float2bfloat16(a - __bfloat162float(ha));
    __nv_bfloat16 lb = __float2bfloat16(b - __bfloat162float(hb));
    hi = (unsigned)__bfloat16_as_ushort(ha) | ((unsigned)__bfloat16_as_ushort(hb) << 16);
    lo = (unsigned)__bfloat16_as_ushort(la) | ((unsigned)__bfloat16_as_ushort(lb) << 16);
}

// ------------------- weight fragment prep -------------------
__global__ void prep_wfrag(const float* W12, const float* W21, const float* W22,
                           const float* W31, const float* W32) {
    const float* Ws[5] = {W12, W21, W22, W31, W32};
    int m = blockIdx.y;
    const float* W = Ws[m];
    int idx = blockIdx.x * 256 + threadIdx.x;
    int lane = idx & 31, ks = (idx >> 5) & 7, nt = idx >> 8;
    int n = nt * 8 + (lane >> 2);
    int k0 = ks * 16 + (lane & 3) * 2;
    unsigned h0, l0, h1, l1;
    pk_split(W[k0 * HID + n], W[(k0 + 1) * HID + n], h0, l0);
    pk_split(W[(k0 + 8) * HID + n], W[(k0 + 9) * HID + n], h1, l1);
    g_wfhi[m * 4096 + idx] = make_uint2(h0, h1);
    g_wflo[m * 4096 + idx] = make_uint2(l0, l1);
}

// ------------------- utility -------------------
__global__ void zero_misc() {
    int i = blockIdx.x * blockDim.x + threadIdx.x;
    if (i < 2 * HID) g_stats[i] = 0.f;
    if (i < N_NODES) g_cnti[i] = 0;
}

// ------------------- CSC build -------------------
__global__ void csr_hist(const int* __restrict__ ei) {
    int e = blockIdx.x * blockDim.x + threadIdx.x;
    if (e < N_EDGES) atomicAdd(&g_cnti[ei[N_EDGES + e]], 1);
}

__global__ void scan1() {
    __shared__ int warpsum[32];
    int i = blockIdx.x * SCB + threadIdx.x;
    int lane = threadIdx.x & 31, wid = threadIdx.x >> 5;
    int v = (i < N_NODES) ? g_cnti[i] : 0;
    int s = v;
#pragma unroll
    for (int o = 1; o < 32; o <<= 1) {
        int t = __shfl_up_sync(0xffffffffu, s, o);
        if (lane >= o) s += t;
    }
    if (lane == 31) warpsum[wid] = s;
    __syncthreads();
    if (wid == 0) {
        int ws = warpsum[lane];
#pragma unroll
        for (int o = 1; o < 32; o <<= 1) {
            int t = __shfl_up_sync(0xffffffffu, ws, o);
            if (lane >= o) ws += t;
        }
        warpsum[lane] = ws;
    }
    __syncthreads();
    int total = s + (wid > 0 ? warpsum[wid - 1] : 0);
    if (i < N_NODES) g_off[i] = total - v;   // exclusive within block
    if (threadIdx.x == SCB - 1) g_bsum[blockIdx.x] = total;
}

// scan3 with scan2 merged: each block prefix-sums the 49 block sums locally.
__global__ void scan3() {
    __shared__ int bs[64];
    int tid = threadIdx.x;
    if (tid < 64) bs[tid] = (tid < NSCB) ? g_bsum[tid] : 0;
    __syncthreads();
    for (int o = 1; o < 64; o <<= 1) {
        int t = (tid < 64 && tid >= o) ? bs[tid - o] : 0;
        __syncthreads();
        if (tid < 64) bs[tid] += t;
        __syncthreads();
    }
    int i = blockIdx.x * blockDim.x + tid;
    if (i < N_NODES) {
        int blk = i / SCB;
        int pre = (blk > 0) ? bs[blk - 1] : 0;
        int o = g_off[i] + pre;
        g_off[i] = o;
        g_fill[i] = o;
    }
    if (i == 0) g_off[N_NODES] = N_EDGES;
}

// scatter sorted edge records: one float4 per edge {src_bits, ea0, ea1, ea2}
__global__ void csr_scatter(const int* __restrict__ ei, const float* __restrict__ ea) {
    int e = blockIdx.x * blockDim.x + threadIdx.x;
    if (e < N_EDGES) {
        int d = ei[N_EDGES + e];
        int s = ei[e];
        float a0 = ea[e * 3], a1 = ea[e * 3 + 1], a2 = ea[e * 3 + 2];
        int p = atomicAdd(&g_fill[d], 1);
        g_edge[p] = make_float4(__int_as_float(s), a0, a1, a2);
    }
}

// ------------------- tensor GEMM core pieces -------------------
#define AROW 136

__device__ __forceinline__ void tensor_gemm(const ushort_t* Ahi, const ushort_t* Alo,
                                            const uint2* __restrict__ wfhi,
                                            const uint2* __restrict__ wflo,
                                            const float* __restrict__ bias,
                                            int warp, int lane, float acc[8][4]) {
    int mw = warp & 3, nh = warp >> 2;
    int grp = lane >> 2, qk = lane & 3;
#pragma unroll
    for (int nt = 0; nt < 8; nt++) {
        int cc = nh * 64 + nt * 8 + qk * 2;
        float b0 = bias[cc], b1v = bias[cc + 1];
        acc[nt][0] = b0; acc[nt][1] = b1v; acc[nt][2] = b0; acc[nt][3] = b1v;
    }
    int arow = (mw * 16 + grp) * AROW;
#pragma unroll 2
    for (int ks = 0; ks < 8; ks++) {
        int ab = arow + ks * 16 + qk * 2;
        unsigned ah0 = *reinterpret_cast<const unsigned*>(Ahi + ab);
        unsigned ah1 = *reinterpret_cast<const unsigned*>(Ahi + ab + 8 * AROW);
        unsigned ah2 = *reinterpret_cast<const unsigned*>(Ahi + ab + 8);
        unsigned ah3 = *reinterpret_cast<const unsigned*>(Ahi + ab + 8 * AROW + 8);
        unsigned al0 = *reinterpret_cast<const unsigned*>(Alo + ab);
        unsigned al1 = *reinterpret_cast<const unsigned*>(Alo + ab + 8 * AROW);
        unsigned al2 = *reinterpret_cast<const unsigned*>(Alo + ab + 8);
        unsigned al3 = *reinterpret_cast<const unsigned*>(Alo + ab + 8 * AROW + 8);
        const uint2* ph = wfhi + ((nh * 8) * 8 + ks) * 32 + lane;
        const uint2* pl = wflo + ((nh * 8) * 8 + ks) * 32 + lane;
#pragma unroll
        for (int nt = 0; nt < 8; nt++) {
            uint2 bh = ph[nt * 256];
            uint2 bl = pl[nt * 256];
            mma16816(acc[nt], ah0, ah1, ah2, ah3, bh.x, bh.y);
            mma16816(acc[nt], ah0, ah1, ah2, ah3, bl.x, bl.y);
            mma16816(acc[nt], al0, al1, al2, al3, bh.x, bh.y);
        }
    }
}

// relu + bf16-split + store acc into (reused) A smem
__device__ __forceinline__ void store_T(ushort_t* Thi, ushort_t* Tlo,
                                        int warp, int lane, float acc[8][4]) {
    int mw = warp & 3, nh = warp >> 2;
    int grp = lane >> 2, qk = lane & 3;
    int r0 = (mw * 16 + grp) * AROW, r1 = r0 + 8 * AROW;
#pragma unroll
    for (int nt = 0; nt < 8; nt++) {
        int cc = nh * 64 + nt * 8 + qk * 2;
        unsigned hi, lo;
        pk_split(fmaxf(acc[nt][0], 0.f), fmaxf(acc[nt][1], 0.f), hi, lo);
        *reinterpret_cast<unsigned*>(Thi + r0 + cc) = hi;
        *reinterpret_cast<unsigned*>(Tlo + r0 + cc) = lo;
        pk_split(fmaxf(acc[nt][2], 0.f), fmaxf(acc[nt][3], 0.f), hi, lo);
        *reinterpret_cast<unsigned*>(Thi + r1 + cc) = hi;
        *reinterpret_cast<unsigned*>(Tlo + r1 + cc) = lo;
    }
}

__device__ __forceinline__ void epilogue(float* __restrict__ hout,
                                         float* ssum, float* ssq, int base,
                                         int warp, int lane, float acc[8][4]) {
    int mw = warp & 3, nh = warp >> 2;
    int grp = lane >> 2, qk = lane & 3;
    int r0 = base + mw * 16 + grp, r1 = r0 + 8;
    bool v0 = r0 < N_NODES, v1 = r1 < N_NODES;
#pragma unroll
    for (int nt = 0; nt < 8; nt++) {
        int cc = nh * 64 + nt * 8 + qk * 2;
        float f0 = acc[nt][0], f1 = acc[nt][1], f2 = acc[nt][2], f3 = acc[nt][3];
        if (v0) *reinterpret_cast<float2*>(hout + (size_t)r0 * HID + cc) = make_float2(f0, f1);
        if (v1) *reinterpret_cast<float2*>(hout + (size_t)r1 * HID + cc) = make_float2(f2, f3);
        float s0 = (v0 ? f0 : 0.f) + (v1 ? f2 : 0.f);
        float s1 = (v0 ? f1 : 0.f) + (v1 ? f3 : 0.f);
        float q0 = (v0 ? f0 * f0 : 0.f) + (v1 ? f2 * f2 : 0.f);
        float q1 = (v0 ? f1 * f1 : 0.f) + (v1 ? f3 * f3 : 0.f);
        atomicAdd(&ssum[cc], s0);
        atomicAdd(&ssum[cc + 1], s1);
        atomicAdd(&ssq[cc], q0);
        atomicAdd(&ssq[cc + 1], q1);
    }
}

// ------------------- FUSED node kernel, layers 2/3 (3 blocks/SM — register-optimal) ----------
__global__ void __launch_bounds__(256, 3)
node_fused(const float* __restrict__ hsrc, float* __restrict__ hdst,
           const float* __restrict__ We, const float* __restrict__ be,
           const uint2* __restrict__ wfhi1, const uint2* __restrict__ wflo1, const float* __restrict__ b1,
           const uint2* __restrict__ wfhi2, const uint2* __restrict__ wflo2, const float* __restrict__ b2) {
    extern __shared__ __align__(16) char smemc[];
    ushort_t* Ahi = reinterpret_cast<ushort_t*>(smemc);
    ushort_t* Alo = Ahi + 64 * AROW;
    float* ssum = reinterpret_cast<float*>(Alo + 64 * AROW);
    float* ssq = ssum + HID;
    int tid = threadIdx.x;
    int base = blockIdx.x * 64;
    if (tid < HID) { ssum[tid] = 0.f; ssq[tid] = 0.f; }

    int warp = tid >> 5, lane = tid & 31;
    int c = lane * 4;
    {
        float4 w0 = *reinterpret_cast<const float4*>(We + c);
        float4 w1 = *reinterpret_cast<const float4*>(We + HID + c);
        float4 w2 = *reinterpret_cast<const float4*>(We + 2 * HID + c);
        float4 b4 = *reinterpret_cast<const float4*>(be + c);
        float4 sc4 = *reinterpret_cast<const float4*>(g_scale + c);
        float4 sh4 = *reinterpret_cast<const float4*>(g_shift + c);

        for (int rr = 0; rr < 8; rr++) {
            int r = warp * 8 + rr;
            int n = base + r;
            float ax = 0.f, ay = 0.f, az = 0.f, aw = 0.f;
            if (n < N_NODES) {
                float4 own = *reinterpret_cast<const float4*>(hsrc + (size_t)n * HID + c);
                ax = fmaxf(own.x * sc4.x + sh4.x, 0.f);
                ay = fmaxf(own.y * sc4.y + sh4.y, 0.f);
                az = fmaxf(own.z * sc4.z + sh4.z, 0.f);
                aw = fmaxf(own.w * sc4.w + sh4.w, 0.f);
                int beg = g_off[n], end = g_off[n + 1];
                int j = beg;
                for (; j + 4 <= end; j += 4) {
                    float4 E0 = g_edge[j], E1 = g_edge[j + 1], E2 = g_edge[j + 2], E3 = g_edge[j + 3];
                    float4 h0 = *reinterpret_cast<const float4*>(hsrc + (size_t)__float_as_int(E0.x) * HID + c);
                    float4 h1 = *reinterpret_cast<const float4*>(hsrc + (size_t)__float_as_int(E1.x) * HID + c);
                    float4 h2 = *reinterpret_cast<const float4*>(hsrc + (size_t)__float_as_int(E2.x) * HID + c);
                    float4 h3 = *reinterpret_cast<const float4*>(hsrc + (size_t)__float_as_int(E3.x) * HID + c);
#pragma unroll
                    for (int u = 0; u < 4; u++) {
                        float4 E = (u == 0) ? E0 : (u == 1) ? E1 : (u == 2) ? E2 : E3;
                        float4 hh = (u == 0) ? h0 : (u == 1) ? h1 : (u == 2) ? h2 : h3;
                        float hx = fmaxf(hh.x * sc4.x + sh4.x, 0.f);
                        float hy = fmaxf(hh.y * sc4.y + sh4.y, 0.f);
                        float hz = fmaxf(hh.z * sc4.z + sh4.z, 0.f);
                        float hw = fmaxf(hh.w * sc4.w + sh4.w, 0.f);
                        ax += fmaxf(hx + E.y * w0.x + E.z * w1.x + E.w * w2.x + b4.x, 0.f);
                        ay += fmaxf(hy + E.y * w0.y + E.z * w1.y + E.w * w2.y + b4.y, 0.f);
                        az += fmaxf(hz + E.y * w0.z + E.z * w1.z + E.w * w2.z + b4.z, 0.f);
                        aw += fmaxf(hw + E.y * w0.w + E.z * w1.w + E.w * w2.w + b4.w, 0.f);
                    }
                }
                for (; j < end; j++) {
                    float4 E = g_edge[j];
                    float4 hh = *reinterpret_cast<const float4*>(hsrc + (size_t)__float_as_int(E.x) * HID + c);
                    float hx = fmaxf(hh.x * sc4.x + sh4.x, 0.f);
                    float hy = fmaxf(hh.y * sc4.y + sh4.y, 0.f);
                    float hz = fmaxf(hh.z * sc4.z + sh4.z, 0.f);
                    float hw = fmaxf(hh.w * sc4.w + sh4.w, 0.f);
                    ax += fmaxf(hx + E.y * w0.x + E.z * w1.x + E.w * w2.x + b4.x, 0.f);
                    ay += fmaxf(hy + E.y * w0.y + E.z * w1.y + E.w * w2.y + b4.y, 0.f);
                    az += fmaxf(hz + E.y * w0.z + E.z * w1.z + E.w * w2.z + b4.z, 0.f);
                    aw += fmaxf(hw + E.y * w0.w + E.z * w1.w + E.w * w2.w + b4.w, 0.f);
                }
            }
            unsigned h01, l01, h23, l23;
            pk_split(ax, ay, h01, l01);
            pk_split(az, aw, h23, l23);
            unsigned* dh = reinterpret_cast<unsigned*>(Ahi + r * AROW + c);
            dh[0] = h01; dh[1] = h23;
            unsigned* dl = reinterpret_cast<unsigned*>(Alo + r * AROW + c);
            dl[0] = l01; dl[1] = l23;
        }
    }
    __syncthreads();

    float acc[8][4];
    tensor_gemm(Ahi, Alo, wfhi1, wflo1, b1, warp, lane, acc);
    __syncthreads();                        // everyone done reading A
    store_T(Ahi, Alo, warp, lane, acc);     // overwrite A with relu(T)
    __syncthreads();
    tensor_gemm(Ahi, Alo, wfhi2, wflo2, b2, warp, lane, acc);
    epilogue(hdst, ssum, ssq, base, warp, lane, acc);
    __syncthreads();
    if (tid < HID) {
        atomicAdd(&g_stats[tid], ssum[tid]);
        atomicAdd(&g_stats[HID + tid], ssq[tid]);
    }
}

// ------------------- FUSED node kernel, layer 1 (gather7 + scalar GEMM1 + tensor GEMM2) ----------
__global__ void __launch_bounds__(256, 3)
node1(const float* __restrict__ x, float* __restrict__ hout,
      const float* __restrict__ We, const float* __restrict__ be,
      const float* __restrict__ W11, const float* __restrict__ b1,
      const uint2* __restrict__ wfhi2, const uint2* __restrict__ wflo2, const float* __restrict__ b2) {
    extern __shared__ __align__(16) char smemc[];
    ushort_t* Thi = reinterpret_cast<ushort_t*>(smemc);
    ushort_t* Tlo = Thi + 64 * AROW;
    float* As7 = reinterpret_cast<float*>(Tlo + 64 * AROW);   // [64][8]
    float* sWe = As7 + 64 * 8;                                 // [3*7]
    float* sbe = sWe + 3 * IN_DIM;                             // [7]
    float* sW1 = sbe + IN_DIM;                                 // [7][128]
    float* ssum = sW1 + IN_DIM * HID;
    float* ssq = ssum + HID;
    int tid = threadIdx.x;
    int base = blockIdx.x * 64;
    if (tid < HID) { ssum[tid] = 0.f; ssq[tid] = 0.f; }
    if (tid < 3 * IN_DIM) sWe[tid] = We[tid];
    if (tid >= 32 && tid < 32 + IN_DIM) sbe[tid - 32] = be[tid - 32];
    for (int i = tid; i < IN_DIM * HID; i += 256) sW1[i] = W11[i];
    __syncthreads();

    // ---- gather phase: 4 threads per node ----
    {
        int r = tid >> 2, sub = tid & 3;
        int n = base + r;
        float acc[IN_DIM];
#pragma unroll
        for (int k = 0; k < IN_DIM; k++) acc[k] = 0.f;
        if (n < N_NODES) {
            int beg = g_off[n], end = g_off[n + 1];
            for (int j = beg + sub; j < end; j += 4) {
                float4 E = g_edge[j];
                const float* x0 = x + (size_t)__float_as_int(E.x) * IN_DIM;
#pragma unroll
                for (int k = 0; k < IN_DIM; k++) {
                    float m = x0[k] + E.y * sWe[k] + E.z * sWe[IN_DIM + k] + E.w * sWe[2 * IN_DIM + k] + sbe[k];
                    acc[k] += fmaxf(m, 0.f);
                }
            }
        }
#pragma unroll
        for (int k = 0; k < IN_DIM; k++) {
            acc[k] += __shfl_xor_sync(0xffffffffu, acc[k], 1);
            acc[k] += __shfl_xor_sync(0xffffffffu, acc[k], 2);
        }
        if (sub == 0) {
            if (n < N_NODES) {
                const float* xr = x + (size_t)n * IN_DIM;
#pragma unroll
                for (int k = 0; k < IN_DIM; k++) As7[r * 8 + k] = xr[k] + acc[k];
            } else {
#pragma unroll
                for (int k = 0; k < IN_DIM; k++) As7[r * 8 + k] = 0.f;
            }
            As7[r * 8 + 7] = 0.f;
        }
    }
    __syncthreads();

    int warp = tid >> 5, lane = tid & 31;
    int mw = warp & 3, nh = warp >> 2;
    int grp = lane >> 2, qk = lane & 3;
    float acc[8][4];
#pragma unroll
    for (int nt = 0; nt < 8; nt++) {
        int cc = nh * 64 + nt * 8 + qk * 2;
        float b0 = b1[cc], b1v = b1[cc + 1];
        acc[nt][0] = b0; acc[nt][1] = b1v; acc[nt][2] = b0; acc[nt][3] = b1v;
    }
    int r0l = mw * 16 + grp, r1l = r0l + 8;
#pragma unroll
    for (int k = 0; k < IN_DIM; k++) {
        float a0 = As7[r0l * 8 + k];
        float a1 = As7[r1l * 8 + k];
#pragma unroll
        for (int nt = 0; nt < 8; nt++) {
            int cc = nh * 64 + nt * 8 + qk * 2;
            float w0 = sW1[k * HID + cc], w1 = sW1[k * HID + cc + 1];
            acc[nt][0] += a0 * w0; acc[nt][1] += a0 * w1;
            acc[nt][2] += a1 * w0; acc[nt][3] += a1 * w1;
        }
    }
    store_T(Thi, Tlo, warp, lane, acc);
    __syncthreads();
    tensor_gemm(Thi, Tlo, wfhi2, wflo2, b2, warp, lane, acc);
    epilogue(hout, ssum, ssq, base, warp, lane, acc);
    __syncthreads();
    if (tid < HID) {
        atomicAdd(&g_stats[tid], ssum[tid]);
        atomicAdd(&g_stats[HID + tid], ssq[tid]);
    }
}

// ------------------- BN finalize; zeroes stats for next layer ----------
__global__ void bn_finalize(const float* __restrict__ gamma, const float* __restrict__ beta) {
    int t = threadIdx.x;
    float invN = 1.f / (float)N_NODES;
    float mu = g_stats[t] * invN;
    float var = g_stats[HID + t] * invN - mu * mu;
    float rs = rsqrtf(var + 1e-5f);
    float sc = gamma[t] * rs;
    g_scale[t] = sc;
    g_shift[t] = beta[t] - mu * sc;
    g_stats[t] = 0.f;
    g_stats[HID + t] = 0.f;
}

// ------------------- fused pool + head: block per graph, binary-search node range ----------
__global__ void head_kernel(const int* __restrict__ batch,
                            const float* __restrict__ Wf1, const float* __restrict__ bf1,
                            const float* __restrict__ Wf2, const float* __restrict__ bf2,
                            float* __restrict__ out) {
    __shared__ int lohi[2];
    __shared__ float p[HID];
    __shared__ float red[64];
    int g = blockIdx.x;
    int tid = threadIdx.x;   // 128 threads
    if (tid < 2) {
        int target = g + tid;        // lower_bound(batch, target)
        int lo = 0, hi = N_NODES;
        while (lo < hi) {
            int mid = (lo + hi) >> 1;
            if (batch[mid] < target) lo = mid + 1; else hi = mid;
        }
        lohi[tid] = lo;
    }
    __syncthreads();
    int lo = lohi[0], hi = lohi[1];
    float sc = g_scale[tid], sh = g_shift[tid];
    float s = 0.f;
    for (int n = lo; n < hi; n++)
        s += fmaxf(g_hpre[(size_t)n * HID + tid] * sc + sh, 0.f);
    int cnt = hi - lo;
    p[tid] = s / (float)(cnt > 0 ? cnt : 1);
    __syncthreads();
    if (tid < 64) {
        float acc = bf1[tid];
        for (int k = 0; k < HID; k++) acc += p[k] * Wf1[k * 64 + tid];
        red[tid] = fmaxf(acc, 0.f) * Wf2[tid];
    }
    __syncthreads();
    for (int st = 32; st > 0; st >>= 1) {
        if (tid < st) red[tid] += red[tid + st];
        __syncthreads();
    }
    if (tid == 0) out[g] = red[0] + bf2[0];
}

// ------------------- launch -------------------
extern "C" void kernel_launch(void* const* d_in, const int* in_sizes, int n_in,
                              void* d_out, int out_size) {
    const float* x = (const float*)d_in[0];
    const float* ea = (const float*)d_in[1];
    const int* ei = (const int*)d_in[2];
    const int* batch = (const int*)d_in[3];
    const float* We1 = (const float*)d_in[4];  const float* be1 = (const float*)d_in[5];
    const float* W11 = (const float*)d_in[6];  const float* b11 = (const float*)d_in[7];
    const float* W12 = (const float*)d_in[8];  const float* b12 = (const float*)d_in[9];
    const float* gm1 = (const float*)d_in[10]; const float* bt1 = (const float*)d_in[11];
    const float* We2 = (const float*)d_in[12]; const float* be2 = (const float*)d_in[13];
    const float* W21 = (const float*)d_in[14]; const float* b21 = (const float*)d_in[15];
    const float* W22 = (const float*)d_in[16]; const float* b22 = (const float*)d_in[17];
    const float* gm2 = (const float*)d_in[18]; const float* bt2 = (const float*)d_in[19];
    const float* We3 = (const float*)d_in[20]; const float* be3 = (const float*)d_in[21];
    const float* W31 = (const float*)d_in[22]; const float* b31 = (const float*)d_in[23];
    const float* W32 = (const float*)d_in[24]; const float* b32 = (const float*)d_in[25];
    const float* gm3 = (const float*)d_in[26]; const float* bt3 = (const float*)d_in[27];
    const float* Wf1 = (const float*)d_in[28]; const float* bf1 = (const float*)d_in[29];
    const float* Wf2 = (const float*)d_in[30]; const float* bf2 = (const float*)d_in[31];
    float* out = (float*)d_out;

    float *p_hpre, *p_hpre2;
    cudaGetSymbolAddress((void**)&p_hpre, g_hpre);
    cudaGetSymbolAddress((void**)&p_hpre2, g_hpre2);
    uint2 *p_wfhi, *p_wflo;
    cudaGetSymbolAddress((void**)&p_wfhi, g_wfhi);
    cudaGetSymbolAddress((void**)&p_wflo, g_wflo);

    const int SMEM_T = 2 * 64 * AROW * 2 + 2 * HID * 4;   // ~35.8KB
    const int SMEM_1 = 2 * 64 * AROW * 2 +
                       (64 * 8 + 3 * IN_DIM + IN_DIM + IN_DIM * HID + 2 * HID) * 4;  // ~41.6KB
    cudaFuncSetAttribute((const void*)node_fused, cudaFuncAttributeMaxDynamicSharedMemorySize, SMEM_T);
    cudaFuncSetAttribute((const void*)node1, cudaFuncAttributeMaxDynamicSharedMemorySize, SMEM_1);

    const int nodeBlocks = (N_NODES + 63) / 64;

    // ---------- init + CSC build ----------
    prep_wfrag<<<dim3(16, 5), 256>>>(W12, W21, W22, W31, W32);
    zero_misc<<<(N_NODES + 255) / 256, 256>>>();
    csr_hist<<<(N_EDGES + 255) / 256, 256>>>(ei);
    scan1<<<NSCB, SCB>>>();
    scan3<<<(N_NODES + 255) / 256, 256>>>();
    csr_scatter<<<(N_EDGES + 255) / 256, 256>>>(ei, ea);

    // ---------- layer 1 (fully fused) ----------
    node1<<<nodeBlocks, 256, SMEM_1>>>(x, p_hpre, We1, be1, W11, b11,
                                       p_wfhi + 0 * 4096, p_wflo + 0 * 4096, b12);
    bn_finalize<<<1, HID>>>(gm1, bt1);

    // ---------- layer 2 (fused gather + MLP; hpre -> hpre2) ----------
    node_fused<<<nodeBlocks, 256, SMEM_T>>>(p_hpre, p_hpre2, We2, be2,
                                            p_wfhi + 1 * 4096, p_wflo + 1 * 4096, b21,
                                            p_wfhi + 2 * 4096, p_wflo + 2 * 4096, b22);
    bn_finalize<<<1, HID>>>(gm2, bt2);

    // ---------- layer 3 (fused; hpre2 -> hpre) ----------
    node_fused<<<nodeBlocks, 256, SMEM_T>>>(p_hpre2, p_hpre, We3, be3,
                                            p_wfhi + 3 * 4096, p_wflo + 3 * 4096, b31,
                                            p_wfhi + 4 * 4096, p_wflo + 4 * 4096, b32);
    bn_finalize<<<1, HID>>>(gm3, bt3);

    // ---------- fused pool + head ----------
    head_kernel<<<N_GRAPHS, HID>>>(batch, Wf1, bf1, Wf2, bf2, out);
}